// round 14
// baseline (speedup 1.0000x reference)
#include <cuda_runtime.h>
#include <math.h>

#define LQ    1024
#define CD    256
#define NH    8
#define NL    4
#define NLOG  272          // 16 deform + 256 add-key logits
#define SEG   528          // 256 kw + 256 attn_add + 1 sa + 15 pad (stays zero)
#define KTOT  (NH*SEG)     // 4224
#define KH0   272
#define KH1   256

typedef unsigned long long ull;

__device__ __forceinline__ ull f2fma(ull a, ull b, ull c) {
    ull d; asm("fma.rn.f32x2 %0, %1, %2, %3;" : "=l"(d) : "l"(a), "l"(b), "l"(c)); return d;
}
__device__ __forceinline__ ull splat2(float x) {
    ull d; asm("mov.b64 %0, {%1, %1};" : "=l"(d) : "f"(x)); return d;
}
__device__ __forceinline__ void unpack2(ull v, float& lo, float& hi) {
    asm("mov.b64 {%0, %1}, %2;" : "=f"(lo), "=f"(hi) : "l"(v));
}
__device__ __forceinline__ void cpasync16(unsigned s, const void* g) {
    asm volatile("cp.async.cg.shared.global [%0], [%1], 16;" :: "r"(s), "l"(g));
}
#define CP_COMMIT() asm volatile("cp.async.commit_group;" ::: "memory")
#define CP_WAIT0()  asm volatile("cp.async.wait_group 0;" ::: "memory")

// ---------------- scratch ----------------
__device__ __align__(16) float g_hw[9*CD];
__device__ __align__(16) float g_off[LQ*CD];
__device__ __align__(16) int   g_fidx[NH*16*LQ];
__device__ __align__(16) float g_logits[NH*NLOG*LQ];    // K-half-0 partial logits
__device__ __align__(16) float g_logits2[NH*NLOG*LQ];   // K-half-1 partial logits
__device__ __align__(16) float g_A2[NH*CD*CD];
__device__ __align__(16) float g_A[LQ*KTOT];
__device__ __align__(16) float g_B[KTOT*CD];
__device__ __align__(16) float g_Cpart[NH*2*LQ*CD];

struct GSmem {
    float As[2][16][64];     // 8.2 KB
    float Bs[2][16][264];    // 33.8 KB  -> total 42 KB, 2 CTA/SM fits
};

// Thread column mapping (all GEMMs + epilogues):
//   j0 = (tid & 31) * 4 ; thread owns cols [j0, j0+4) and [j0+128, j0+132)
//   -> LDS.128 lane stride 16B: conflict-free smem reads.

// ---------------- 64x256 GEMM core (K mult of 16) ----------------
// MODE 0: acc += A[64xK] * B^T (B row-major [256][K]; reg prefetch)
// MODE 1: acc += A[64xK] * B   (B row-major [K][256]; cp.async)
// MODE 2: MODE 1 with gathered rows IF[gidx[k]]
template<int MODE>
__device__ __forceinline__ void gemm_core(
    GSmem* sm,
    const float* __restrict__ A, int a_row_stride,
    const float* __restrict__ B, int ldb,
    const int* __restrict__ gidx, const float* __restrict__ IF,
    int K, ull acc[8][4])
{
    const int tid  = threadIdx.x;
    const int mrow = (tid >> 5) << 3;
    const int j0   = (tid & 31) << 2;
#pragma unroll
    for (int i = 0; i < 8; i++)
#pragma unroll
        for (int j = 0; j < 4; j++) acc[i][j] = 0ull;

    const int ar = tid >> 2, ac = (tid & 3) << 2;
    const int brow = tid >> 4, bcol = (tid & 15) << 2;
    unsigned bs_sm[2];
    bs_sm[0] = (unsigned)__cvta_generic_to_shared(&sm->Bs[0][brow][bcol]);
    bs_sm[1] = (unsigned)__cvta_generic_to_shared(&sm->Bs[1][brow][bcol]);

    float4 pa, pb0, pb1, pb2, pb3;

    // ---- prologue: tile 0 ----
    pa = *(const float4*)(A + (size_t)ar * a_row_stride + ac);
    if (MODE == 0) {
        const float* br = B + (size_t)tid * ldb;
        pb0 = ((const float4*)br)[0]; pb1 = ((const float4*)br)[1];
        pb2 = ((const float4*)br)[2]; pb3 = ((const float4*)br)[3];
        sm->Bs[0][0][tid]  = pb0.x; sm->Bs[0][1][tid]  = pb0.y; sm->Bs[0][2][tid]  = pb0.z; sm->Bs[0][3][tid]  = pb0.w;
        sm->Bs[0][4][tid]  = pb1.x; sm->Bs[0][5][tid]  = pb1.y; sm->Bs[0][6][tid]  = pb1.z; sm->Bs[0][7][tid]  = pb1.w;
        sm->Bs[0][8][tid]  = pb2.x; sm->Bs[0][9][tid]  = pb2.y; sm->Bs[0][10][tid] = pb2.z; sm->Bs[0][11][tid] = pb2.w;
        sm->Bs[0][12][tid] = pb3.x; sm->Bs[0][13][tid] = pb3.y; sm->Bs[0][14][tid] = pb3.z; sm->Bs[0][15][tid] = pb3.w;
    } else {
        const float* br = (MODE == 2) ? (IF + (size_t)gidx[brow] * CD)
                                      : (B + (size_t)brow * ldb);
#pragma unroll
        for (int i = 0; i < 4; i++)
            cpasync16(bs_sm[0] + i * 256, br + bcol + i * 64);
        CP_COMMIT();
        CP_WAIT0();
    }
    sm->As[0][ac + 0][ar] = pa.x; sm->As[0][ac + 1][ar] = pa.y;
    sm->As[0][ac + 2][ar] = pa.z; sm->As[0][ac + 3][ar] = pa.w;
    __syncthreads();

    int buf = 0;
    for (int k0 = 16;; k0 += 16) {
        const bool more = (k0 < K);
        const int nb = buf ^ 1;
        if (more) {
            pa = *(const float4*)(A + (size_t)ar * a_row_stride + k0 + ac);
            if (MODE == 0) {
                const float* br = B + (size_t)tid * ldb + k0;
                pb0 = ((const float4*)br)[0]; pb1 = ((const float4*)br)[1];
                pb2 = ((const float4*)br)[2]; pb3 = ((const float4*)br)[3];
            } else {
                const float* br = (MODE == 2) ? (IF + (size_t)gidx[k0 + brow] * CD)
                                              : (B + (size_t)(k0 + brow) * ldb);
#pragma unroll
                for (int i = 0; i < 4; i++)
                    cpasync16(bs_sm[nb] + i * 256, br + bcol + i * 64);
                CP_COMMIT();
            }
        }
#pragma unroll
        for (int k = 0; k < 16; k++) {
            float4 av0 = *(const float4*)&sm->As[buf][k][mrow];
            float4 av1 = *(const float4*)&sm->As[buf][k][mrow + 4];
            ulonglong2 bl0 = *(const ulonglong2*)&sm->Bs[buf][k][j0];
            ulonglong2 bl1 = *(const ulonglong2*)&sm->Bs[buf][k][j0 + 128];
            ull b0 = bl0.x, b1 = bl0.y, b2 = bl1.x, b3 = bl1.y;
            float a8[8] = {av0.x, av0.y, av0.z, av0.w, av1.x, av1.y, av1.z, av1.w};
#pragma unroll
            for (int i = 0; i < 8; i++) {
                ull ai = splat2(a8[i]);
                acc[i][0] = f2fma(ai, b0, acc[i][0]);
                acc[i][1] = f2fma(ai, b1, acc[i][1]);
                acc[i][2] = f2fma(ai, b2, acc[i][2]);
                acc[i][3] = f2fma(ai, b3, acc[i][3]);
            }
        }
        if (!more) break;
        sm->As[nb][ac + 0][ar] = pa.x; sm->As[nb][ac + 1][ar] = pa.y;
        sm->As[nb][ac + 2][ar] = pa.z; sm->As[nb][ac + 3][ar] = pa.w;
        if (MODE == 0) {
            sm->Bs[nb][0][tid]  = pb0.x; sm->Bs[nb][1][tid]  = pb0.y; sm->Bs[nb][2][tid]  = pb0.z; sm->Bs[nb][3][tid]  = pb0.w;
            sm->Bs[nb][4][tid]  = pb1.x; sm->Bs[nb][5][tid]  = pb1.y; sm->Bs[nb][6][tid]  = pb1.z; sm->Bs[nb][7][tid]  = pb1.w;
            sm->Bs[nb][8][tid]  = pb2.x; sm->Bs[nb][9][tid]  = pb2.y; sm->Bs[nb][10][tid] = pb2.z; sm->Bs[nb][11][tid] = pb2.w;
            sm->Bs[nb][12][tid] = pb3.x; sm->Bs[nb][13][tid] = pb3.y; sm->Bs[nb][14][tid] = pb3.z; sm->Bs[nb][15][tid] = pb3.w;
        } else {
            CP_WAIT0();
        }
        __syncthreads();
        buf = nb;
    }
}

// columns: [j0, j0+4) from acc[.][0..1], [j0+128, j0+132) from acc[.][2..3]
__device__ __forceinline__ void store_tile(ull acc[8][4], float* __restrict__ C,
                                           int ldc, const float* __restrict__ bias) {
    const int tid  = threadIdx.x;
    const int mrow = (tid >> 5) << 3;
    const int j0   = (tid & 31) << 2;
#pragma unroll
    for (int i = 0; i < 8; i++) {
        float o[8];
#pragma unroll
        for (int jj = 0; jj < 4; jj++) unpack2(acc[i][jj], o[2*jj], o[2*jj+1]);
        if (bias) {
#pragma unroll
            for (int j = 0; j < 4; j++) o[j] += bias[j0 + j];
#pragma unroll
            for (int j = 4; j < 8; j++) o[j] += bias[j0 + 124 + j];   // 128 + j0 + (j-4)
        }
        float* cr = C + (size_t)(mrow + i) * ldc;
        *(float4*)(cr + j0)       = *(const float4*)(o + 0);
        *(float4*)(cr + j0 + 128) = *(const float4*)(o + 4);
    }
}

// ---------------- kernels ----------------

// L1 (594 blocks):
//   [0,16)    off = q @ Woff^T + boff
//   16        head-mix softmax
//   [17,49)   A2 GEMMs
//   [49,81)   v2 GEMMs -> stored DIRECTLY into g_B rows [256,512) (no hw)
//   [81,593)  Wval^T transpose tiles -> g_B rows [0,256) (no hw)
//   593       bias rows -> g_B row 512 per head (no hw)
__global__ void __launch_bounds__(256, 2) k_pre(const float* __restrict__ q,
                                                const float* __restrict__ Woff,
                                                const float* __restrict__ boff,
                                                const float* __restrict__ Wmix,
                                                const float* __restrict__ addk,
                                                const float* __restrict__ Wattn,
                                                const float* __restrict__ Wval,
                                                const float* __restrict__ bval) {
    __shared__ GSmem sm;
    ull acc[8][4];
    int b = blockIdx.x;
    int tid = threadIdx.x;
    if (b < 16) {
        gemm_core<0>(&sm, q + (size_t)b * 64 * CD, CD, Woff, CD, nullptr, nullptr, CD, acc);
        store_tile(acc, g_off + (size_t)b * 64 * CD, CD, boff);
    } else if (b == 16) {
        int c = tid;
        float v[9], m = -1e30f;
#pragma unroll
        for (int j = 0; j < 9; j++) { v[j] = Wmix[c * 9 + j]; m = fmaxf(m, v[j]); }
        float s = 0.f;
#pragma unroll
        for (int j = 0; j < 9; j++) { v[j] = expf(v[j] - m); s += v[j]; }
        float inv = 1.f / s;
#pragma unroll
        for (int j = 0; j < 9; j++) g_hw[j * CD + c] = v[j] * inv;
    } else if (b < 49) {
        int bb = b - 17;
        int mat = bb >> 2, mt = bb & 3;
        gemm_core<0>(&sm, addk + (size_t)mt * 64 * CD, CD,
                     Wattn + (size_t)(mat * 4 + 4) * CD * CD, CD,
                     nullptr, nullptr, CD, acc);
        store_tile(acc, g_A2 + (size_t)mat * CD * CD + mt * 64 * CD, CD, nullptr);
    } else if (b < 81) {
        int bb = b - 49;
        int h = bb >> 2, mt = bb & 3;
        gemm_core<0>(&sm, addk + (size_t)mt * 64 * CD, CD,
                     Wval + (size_t)(2 * h + 1) * CD * CD, CD,
                     nullptr, nullptr, CD, acc);
        // v2 rows go straight to g_B segment [256,512) of head h (unscaled)
        store_tile(acc, g_B + ((size_t)h * SEG + 256 + mt * 64) * CD, CD,
                   bval + (2 * h + 1) * CD);
    } else if (b < 593) {
        int bb = b - 81;
        float (*tile)[33] = (float(*)[33])(&sm.As[0][0][0]);   // reuse smem
        int h  = bb >> 6;
        int t  = bb & 63;
        int rt = t >> 3, ct = t & 7;
        int r0 = rt * 32, c0 = ct * 32;
        int rr = tid & 31, cl = tid >> 5;
#pragma unroll
        for (int i = 0; i < 4; i++) {
            int cc = cl + i * 8;
            tile[cc][rr] = Wval[((size_t)(2 * h) * CD + (c0 + cc)) * CD + (r0 + rr)];
        }
        __syncthreads();
        int cc2 = tid & 31, rl = tid >> 5;
#pragma unroll
        for (int i = 0; i < 4; i++) {
            int rr2 = rl + i * 8;
            g_B[((size_t)h * SEG + (r0 + rr2)) * CD + (c0 + cc2)] = tile[cc2][rr2];
        }
    } else {
        int c = tid;
#pragma unroll
        for (int h = 0; h < NH; h++)
            g_B[((size_t)h * SEG + 512) * CD + c] = bval[(2 * h) * CD + c];
    }
}

__global__ void __launch_bounds__(256) k_idx(const float* __restrict__ refp,
                                             const int* __restrict__ iss,
                                             const int* __restrict__ lstart) {
    int gid = blockIdx.x * 256 + threadIdx.x;    // 1024*128
    int lq = gid >> 7, r2 = gid & 127;
    int l = (r2 >> 2) & 3;
    float2 off = *(const float2*)(g_off + (size_t)lq * CD + r2 * 2);
    float2 rp  = *(const float2*)(refp + ((size_t)lq * NL + l) * 2);
    int H = iss[l * 2], W = iss[l * 2 + 1];
    float loc0 = rp.x + off.x / (float)W;   // wh = [W, H]
    float loc1 = rp.y + off.y / (float)H;
    loc0 = fminf(fmaxf(loc0, 0.f), 0.999f);
    loc1 = fminf(fmaxf(loc1, 0.f), 0.999f);
    int i0 = (int)(loc0 * (float)H);        // idx = loc * [H, W]
    int i1 = (int)(loc1 * (float)W);
    int flat = i0 + i1 * H + lstart[l];
    g_fidx[(size_t)r2 * LQ + lq] = flat;    // r2 = h*16 + l*4 + p
}

// L3 (1280 blocks): K-split GEMMs, each half writes partial logits to its buffer.
//   [0,1024):   T GEMM halves + fused deflog: b = hl*32 + half*16 + rcl
//   [1024,1280): add-key logit halves: (half, h, mt, nt)
__global__ void __launch_bounds__(256, 2) k_T_addlog(const float* __restrict__ q,
                                                     const float* __restrict__ IF,
                                                     const float* __restrict__ Wattn) {
    __shared__ GSmem sm;
    ull acc[8][4];
    if (blockIdx.x < 1024) {
        int hl = blockIdx.x >> 5;
        int sub = blockIdx.x & 31;
        int half = sub >> 4, rcl = sub & 15;
        int koff = half * 128;
        float* dst = half ? g_logits2 : g_logits;
        gemm_core<2>(&sm, q + (size_t)rcl * CD + koff, 16 * CD, nullptr, 0,
                     g_fidx + hl * 4096 + rcl * 256 + koff, IF, 128, acc);
        // fused deflog (partial over this K-half):
        //   logit_part[p, lq] = Wattn[hl][p*64 + i, :] . Ttile_part[i, :]
        int h = hl >> 2, l = hl & 3;
        const int tid = threadIdx.x;
        const int mrow = (tid >> 5) << 3;
        const int j0   = (tid & 31) << 2;
        const int lane = tid & 31;
#pragma unroll
        for (int i = 0; i < 8; i++) {
            float o[8];
#pragma unroll
            for (int jj = 0; jj < 4; jj++) unpack2(acc[i][jj], o[2*jj], o[2*jj+1]);
            int ri = mrow + i;
            int lq = rcl + 16 * ri;
#pragma unroll
            for (int p = 0; p < 4; p++) {
                const float* wr = Wattn + (((size_t)hl * 256) + (size_t)(p * 64 + ri)) * CD;
                float4 w0 = *(const float4*)(wr + j0);
                float4 w1 = *(const float4*)(wr + j0 + 128);
                float part = o[0]*w0.x + o[1]*w0.y + o[2]*w0.z + o[3]*w0.w
                           + o[4]*w1.x + o[5]*w1.y + o[6]*w1.z + o[7]*w1.w;
#pragma unroll
                for (int off = 16; off > 0; off >>= 1)
                    part += __shfl_xor_sync(0xffffffffu, part, off);
                if (lane == 0)
                    dst[(size_t)h * NLOG * LQ + (size_t)(l * 4 + p) * LQ + lq] = part;
            }
        }
    } else {
        int b = blockIdx.x - 1024;
        int half = b >> 7;
        int b3 = b & 127;
        int h = b3 >> 4, mt = (b3 >> 2) & 3, nt = b3 & 3;
        int koff = half * 128;
        float* dst = half ? g_logits2 : g_logits;
        gemm_core<0>(&sm, g_A2 + ((size_t)h * CD + mt * 64) * CD + koff, CD,
                     q + (size_t)nt * 256 * CD + koff, CD, nullptr, nullptr, 128, acc);
        store_tile(acc, dst + (size_t)h * NLOG * LQ + (size_t)(16 + mt * 64) * LQ + nt * 256,
                   LQ, nullptr);
    }
}

// L4: fused softmax + kw gather. One warp per (h, lq). Logit = partA + partB.
__global__ void __launch_bounds__(256) k_attn_kw(const float* __restrict__ IF) {
    int warp = threadIdx.x >> 5, lane = threadIdx.x & 31;
    int col = blockIdx.x * 8 + warp;            // 8192 total
    int h = col >> 10, lq = col & 1023;
    const float* baseA = g_logits  + (size_t)h * NLOG * LQ + lq;
    const float* baseB = g_logits2 + (size_t)h * NLOG * LQ + lq;
    float v[9];
    float vmax = -1e30f;
#pragma unroll
    for (int k = 0; k < 9; k++) {
        int s = lane + 32 * k;
        v[k] = (s < NLOG) ? baseA[(size_t)s * LQ] + baseB[(size_t)s * LQ] : -1e30f;
        vmax = fmaxf(vmax, v[k]);
    }
#pragma unroll
    for (int o = 16; o > 0; o >>= 1) vmax = fmaxf(vmax, __shfl_xor_sync(0xffffffffu, vmax, o));
    float sum = 0.f;
#pragma unroll
    for (int k = 0; k < 9; k++) {
        int s = lane + 32 * k;
        v[k] = (s < NLOG) ? expf(v[k] - vmax) : 0.f;
        sum += v[k];
    }
#pragma unroll
    for (int o = 16; o > 0; o >>= 1) sum += __shfl_xor_sync(0xffffffffu, sum, o);
    float inv = 1.f / sum;
    float* arow = g_A + (size_t)lq * KTOT + h * SEG;
    float sa = 0.f;
    float wdef = v[0] * inv;                    // lanes 0..15: deform weights
#pragma unroll
    for (int k = 0; k < 9; k++) {
        int s = lane + 32 * k;
        if (s >= NLOG) continue;
        float w = v[k] * inv;
        if (s < 16) sa += w;                    // keep in register
        else        arow[256 + s - 16] = w;
    }
#pragma unroll
    for (int o = 16; o > 0; o >>= 1) sa += __shfl_xor_sync(0xffffffffu, sa, o);
    if (lane == 0) arow[512] = sa;

    // kw gather: kw[lq, :] = sum_{s<16} wdef_s * IF[fidx[h,s,lq], :]
    int myidx = (lane < 16) ? g_fidx[(h * 16 + lane) * LQ + lq] : 0;
    float acc[8];
#pragma unroll
    for (int j = 0; j < 8; j++) acc[j] = 0.f;
#pragma unroll
    for (int s = 0; s < 16; s++) {
        float w  = __shfl_sync(0xffffffffu, wdef, s);
        int   ix = __shfl_sync(0xffffffffu, myidx, s);
        const float4* row = (const float4*)(IF + (size_t)ix * CD + lane * 8);
        float4 a = row[0], b = row[1];
        acc[0] = fmaf(w, a.x, acc[0]); acc[1] = fmaf(w, a.y, acc[1]);
        acc[2] = fmaf(w, a.z, acc[2]); acc[3] = fmaf(w, a.w, acc[3]);
        acc[4] = fmaf(w, b.x, acc[4]); acc[5] = fmaf(w, b.y, acc[5]);
        acc[6] = fmaf(w, b.z, acc[6]); acc[7] = fmaf(w, b.w, acc[7]);
    }
    float4* out = (float4*)(arow + lane * 8);
    out[0] = make_float4(acc[0], acc[1], acc[2], acc[3]);
    out[1] = make_float4(acc[4], acc[5], acc[6], acc[7]);
}

// fused output GEMM per (head, K-half) -> UNscaled per-(head,half) partials
__global__ void __launch_bounds__(256, 2) k_fused() {
    __shared__ GSmem sm;
    ull acc[8][4];
    int h = blockIdx.x >> 5;
    int sub = blockIdx.x & 31;
    int mt = sub & 15, half = sub >> 4;
    int koff = half ? KH0 : 0;
    int K    = half ? KH1 : KH0;
    gemm_core<1>(&sm, g_A + (size_t)mt * 64 * KTOT + h * SEG + koff, KTOT,
                 g_B + ((size_t)h * SEG + koff) * CD, CD, nullptr, nullptr, K, acc);
    store_tile(acc, g_Cpart + (((size_t)(h * 2 + half) * LQ) + mt * 64) * CD, CD, nullptr);
}

// final: out = q*hw[8] + sum_h hw[h] * (Cpart[2h] + Cpart[2h+1])
__global__ void __launch_bounds__(256) k_out(const float* __restrict__ q,
                                             float* __restrict__ out) {
    int e = blockIdx.x * 256 + threadIdx.x;     // 65536 float4
    int c4 = e & 63;
    float4 qv = ((const float4*)q)[e];
    float4 hw8 = ((const float4*)(g_hw + 8 * CD))[c4];
    float4 r;
    r.x = qv.x * hw8.x; r.y = qv.y * hw8.y; r.z = qv.z * hw8.z; r.w = qv.w * hw8.w;
#pragma unroll
    for (int h = 0; h < NH; h++) {
        float4 hwh = ((const float4*)(g_hw + h * CD))[c4];
        float4 p0 = ((const float4*)(g_Cpart + (size_t)(2 * h) * LQ * CD))[e];
        float4 p1 = ((const float4*)(g_Cpart + (size_t)(2 * h + 1) * LQ * CD))[e];
        r.x = fmaf(hwh.x, p0.x + p1.x, r.x);
        r.y = fmaf(hwh.y, p0.y + p1.y, r.y);
        r.z = fmaf(hwh.z, p0.z + p1.z, r.z);
        r.w = fmaf(hwh.w, p0.w + p1.w, r.w);
    }
    ((float4*)out)[e] = r;
}

extern "C" void kernel_launch(void* const* d_in, const int* in_sizes, int n_in,
                              void* d_out, int out_size) {
    const float* query  = (const float*)d_in[0];
    const float* refp   = (const float*)d_in[1];
    const float* IF     = (const float*)d_in[2];
    const int*   iss    = (const int*)d_in[3];
    const float* addk   = (const float*)d_in[4];
    const int*   lstart = (const int*)d_in[5];
    const float* Woff   = (const float*)d_in[6];
    const float* boff   = (const float*)d_in[7];
    const float* Wattn  = (const float*)d_in[8];
    const float* Wval   = (const float*)d_in[9];
    const float* bval   = (const float*)d_in[10];
    const float* Wmix   = (const float*)d_in[11];
    float* out = (float*)d_out;

    k_pre<<<594, 256>>>(query, Woff, boff, Wmix, addk, Wattn, Wval, bval);
    k_idx<<<512, 256>>>(refp, iss, lstart);
    k_T_addlog<<<1280, 256>>>(query, IF, Wattn);
    k_attn_kw<<<1024, 256>>>(IF);
    k_fused<<<256, 256>>>();
    k_out<<<256, 256>>>(query, out);
}

// round 15
// speedup vs baseline: 1.0171x; 1.0171x over previous
#include <cuda_runtime.h>
#include <math.h>

#define LQ    1024
#define CD    256
#define NH    8
#define NL    4
#define NLOG  272          // 16 deform + 256 add-key logits
#define SEG   528          // 256 kw + 256 attn_add + 1 sa + 15 pad (stays zero)
#define KTOT  (NH*SEG)     // 4224
#define KH0   272
#define KH1   256

typedef unsigned long long ull;

__device__ __forceinline__ ull f2fma(ull a, ull b, ull c) {
    ull d; asm("fma.rn.f32x2 %0, %1, %2, %3;" : "=l"(d) : "l"(a), "l"(b), "l"(c)); return d;
}
__device__ __forceinline__ ull splat2(float x) {
    ull d; asm("mov.b64 %0, {%1, %1};" : "=l"(d) : "f"(x)); return d;
}
__device__ __forceinline__ void unpack2(ull v, float& lo, float& hi) {
    asm("mov.b64 {%0, %1}, %2;" : "=f"(lo), "=f"(hi) : "l"(v));
}
__device__ __forceinline__ void cpasync16(unsigned s, const void* g) {
    asm volatile("cp.async.cg.shared.global [%0], [%1], 16;" :: "r"(s), "l"(g));
}
#define CP_COMMIT() asm volatile("cp.async.commit_group;" ::: "memory")
#define CP_WAIT0()  asm volatile("cp.async.wait_group 0;" ::: "memory")

// ---------------- scratch ----------------
__device__ __align__(16) float g_hw[9*CD];
__device__ __align__(16) float g_off[LQ*CD];
__device__ __align__(16) int   g_fidx[NH*16*LQ];
__device__ __align__(16) float g_logits[NH*NLOG*LQ];
__device__ __align__(16) float g_A2[NH*CD*CD];
__device__ __align__(16) float g_A[LQ*KTOT];
__device__ __align__(16) float g_B[KTOT*CD];
__device__ __align__(16) float g_Cpart[NH*2*LQ*CD];

struct GSmem {
    float As[2][16][64];     // 8.2 KB
    float Bs[2][16][264];    // 33.8 KB  -> total 42 KB, 2 CTA/SM fits
};

// Thread column mapping (all GEMMs + epilogues):
//   j0 = (tid & 31) * 4 ; thread owns cols [j0, j0+4) and [j0+128, j0+132)
//   -> LDS.128 lane stride 16B: conflict-free smem reads.

// ---------------- 64x256 GEMM core (K mult of 16) ----------------
// MODE 0: acc += A[64xK] * B^T (B row-major [256][K]; reg prefetch)
// MODE 1: acc += A[64xK] * B   (B row-major [K][256]; cp.async)
// MODE 2: MODE 1 with gathered rows IF[gidx[k]]
template<int MODE>
__device__ __forceinline__ void gemm_core(
    GSmem* sm,
    const float* __restrict__ A, int a_row_stride,
    const float* __restrict__ B, int ldb,
    const int* __restrict__ gidx, const float* __restrict__ IF,
    int K, ull acc[8][4])
{
    const int tid  = threadIdx.x;
    const int mrow = (tid >> 5) << 3;
    const int j0   = (tid & 31) << 2;
#pragma unroll
    for (int i = 0; i < 8; i++)
#pragma unroll
        for (int j = 0; j < 4; j++) acc[i][j] = 0ull;

    const int ar = tid >> 2, ac = (tid & 3) << 2;
    const int brow = tid >> 4, bcol = (tid & 15) << 2;
    unsigned bs_sm[2];
    bs_sm[0] = (unsigned)__cvta_generic_to_shared(&sm->Bs[0][brow][bcol]);
    bs_sm[1] = (unsigned)__cvta_generic_to_shared(&sm->Bs[1][brow][bcol]);

    float4 pa, pb0, pb1, pb2, pb3;

    // ---- prologue: tile 0 ----
    pa = *(const float4*)(A + (size_t)ar * a_row_stride + ac);
    if (MODE == 0) {
        const float* br = B + (size_t)tid * ldb;
        pb0 = ((const float4*)br)[0]; pb1 = ((const float4*)br)[1];
        pb2 = ((const float4*)br)[2]; pb3 = ((const float4*)br)[3];
        sm->Bs[0][0][tid]  = pb0.x; sm->Bs[0][1][tid]  = pb0.y; sm->Bs[0][2][tid]  = pb0.z; sm->Bs[0][3][tid]  = pb0.w;
        sm->Bs[0][4][tid]  = pb1.x; sm->Bs[0][5][tid]  = pb1.y; sm->Bs[0][6][tid]  = pb1.z; sm->Bs[0][7][tid]  = pb1.w;
        sm->Bs[0][8][tid]  = pb2.x; sm->Bs[0][9][tid]  = pb2.y; sm->Bs[0][10][tid] = pb2.z; sm->Bs[0][11][tid] = pb2.w;
        sm->Bs[0][12][tid] = pb3.x; sm->Bs[0][13][tid] = pb3.y; sm->Bs[0][14][tid] = pb3.z; sm->Bs[0][15][tid] = pb3.w;
    } else {
        const float* br = (MODE == 2) ? (IF + (size_t)gidx[brow] * CD)
                                      : (B + (size_t)brow * ldb);
#pragma unroll
        for (int i = 0; i < 4; i++)
            cpasync16(bs_sm[0] + i * 256, br + bcol + i * 64);
        CP_COMMIT();
        CP_WAIT0();
    }
    sm->As[0][ac + 0][ar] = pa.x; sm->As[0][ac + 1][ar] = pa.y;
    sm->As[0][ac + 2][ar] = pa.z; sm->As[0][ac + 3][ar] = pa.w;
    __syncthreads();

    int buf = 0;
    for (int k0 = 16;; k0 += 16) {
        const bool more = (k0 < K);
        const int nb = buf ^ 1;
        if (more) {
            pa = *(const float4*)(A + (size_t)ar * a_row_stride + k0 + ac);
            if (MODE == 0) {
                const float* br = B + (size_t)tid * ldb + k0;
                pb0 = ((const float4*)br)[0]; pb1 = ((const float4*)br)[1];
                pb2 = ((const float4*)br)[2]; pb3 = ((const float4*)br)[3];
            } else {
                const float* br = (MODE == 2) ? (IF + (size_t)gidx[k0 + brow] * CD)
                                              : (B + (size_t)(k0 + brow) * ldb);
#pragma unroll
                for (int i = 0; i < 4; i++)
                    cpasync16(bs_sm[nb] + i * 256, br + bcol + i * 64);
                CP_COMMIT();
            }
        }
#pragma unroll
        for (int k = 0; k < 16; k++) {
            float4 av0 = *(const float4*)&sm->As[buf][k][mrow];
            float4 av1 = *(const float4*)&sm->As[buf][k][mrow + 4];
            ulonglong2 bl0 = *(const ulonglong2*)&sm->Bs[buf][k][j0];
            ulonglong2 bl1 = *(const ulonglong2*)&sm->Bs[buf][k][j0 + 128];
            ull b0 = bl0.x, b1 = bl0.y, b2 = bl1.x, b3 = bl1.y;
            float a8[8] = {av0.x, av0.y, av0.z, av0.w, av1.x, av1.y, av1.z, av1.w};
#pragma unroll
            for (int i = 0; i < 8; i++) {
                ull ai = splat2(a8[i]);
                acc[i][0] = f2fma(ai, b0, acc[i][0]);
                acc[i][1] = f2fma(ai, b1, acc[i][1]);
                acc[i][2] = f2fma(ai, b2, acc[i][2]);
                acc[i][3] = f2fma(ai, b3, acc[i][3]);
            }
        }
        if (!more) break;
        sm->As[nb][ac + 0][ar] = pa.x; sm->As[nb][ac + 1][ar] = pa.y;
        sm->As[nb][ac + 2][ar] = pa.z; sm->As[nb][ac + 3][ar] = pa.w;
        if (MODE == 0) {
            sm->Bs[nb][0][tid]  = pb0.x; sm->Bs[nb][1][tid]  = pb0.y; sm->Bs[nb][2][tid]  = pb0.z; sm->Bs[nb][3][tid]  = pb0.w;
            sm->Bs[nb][4][tid]  = pb1.x; sm->Bs[nb][5][tid]  = pb1.y; sm->Bs[nb][6][tid]  = pb1.z; sm->Bs[nb][7][tid]  = pb1.w;
            sm->Bs[nb][8][tid]  = pb2.x; sm->Bs[nb][9][tid]  = pb2.y; sm->Bs[nb][10][tid] = pb2.z; sm->Bs[nb][11][tid] = pb2.w;
            sm->Bs[nb][12][tid] = pb3.x; sm->Bs[nb][13][tid] = pb3.y; sm->Bs[nb][14][tid] = pb3.z; sm->Bs[nb][15][tid] = pb3.w;
        } else {
            CP_WAIT0();
        }
        __syncthreads();
        buf = nb;
    }
}

// columns: [j0, j0+4) from acc[.][0..1], [j0+128, j0+132) from acc[.][2..3]
__device__ __forceinline__ void store_tile(ull acc[8][4], float* __restrict__ C,
                                           int ldc, const float* __restrict__ bias) {
    const int tid  = threadIdx.x;
    const int mrow = (tid >> 5) << 3;
    const int j0   = (tid & 31) << 2;
#pragma unroll
    for (int i = 0; i < 8; i++) {
        float o[8];
#pragma unroll
        for (int jj = 0; jj < 4; jj++) unpack2(acc[i][jj], o[2*jj], o[2*jj+1]);
        if (bias) {
#pragma unroll
            for (int j = 0; j < 4; j++) o[j] += bias[j0 + j];
#pragma unroll
            for (int j = 4; j < 8; j++) o[j] += bias[j0 + 124 + j];   // 128 + j0 + (j-4)
        }
        float* cr = C + (size_t)(mrow + i) * ldc;
        *(float4*)(cr + j0)       = *(const float4*)(o + 0);
        *(float4*)(cr + j0 + 128) = *(const float4*)(o + 4);
    }
}

// ---------------- kernels ----------------

// L1 (210 blocks):
//   [0,16)    off = q @ Woff^T + boff
//   16        head-mix softmax
//   [17,49)   A2 GEMMs
//   [49,81)   v2 GEMMs -> stored DIRECTLY into g_B rows [256,512) (no hw)
//   [81,209)  Wval^T transpose, 32x128 per block -> g_B rows [0,256) (no hw)
//   209       bias rows -> g_B row 512 per head (no hw)
__global__ void __launch_bounds__(256, 2) k_pre(const float* __restrict__ q,
                                                const float* __restrict__ Woff,
                                                const float* __restrict__ boff,
                                                const float* __restrict__ Wmix,
                                                const float* __restrict__ addk,
                                                const float* __restrict__ Wattn,
                                                const float* __restrict__ Wval,
                                                const float* __restrict__ bval) {
    __shared__ GSmem sm;
    ull acc[8][4];
    int b = blockIdx.x;
    int tid = threadIdx.x;
    if (b < 16) {
        gemm_core<0>(&sm, q + (size_t)b * 64 * CD, CD, Woff, CD, nullptr, nullptr, CD, acc);
        store_tile(acc, g_off + (size_t)b * 64 * CD, CD, boff);
    } else if (b == 16) {
        int c = tid;
        float v[9], m = -1e30f;
#pragma unroll
        for (int j = 0; j < 9; j++) { v[j] = Wmix[c * 9 + j]; m = fmaxf(m, v[j]); }
        float s = 0.f;
#pragma unroll
        for (int j = 0; j < 9; j++) { v[j] = expf(v[j] - m); s += v[j]; }
        float inv = 1.f / s;
#pragma unroll
        for (int j = 0; j < 9; j++) g_hw[j * CD + c] = v[j] * inv;
    } else if (b < 49) {
        int bb = b - 17;
        int mat = bb >> 2, mt = bb & 3;
        gemm_core<0>(&sm, addk + (size_t)mt * 64 * CD, CD,
                     Wattn + (size_t)(mat * 4 + 4) * CD * CD, CD,
                     nullptr, nullptr, CD, acc);
        store_tile(acc, g_A2 + (size_t)mat * CD * CD + mt * 64 * CD, CD, nullptr);
    } else if (b < 81) {
        int bb = b - 49;
        int h = bb >> 2, mt = bb & 3;
        gemm_core<0>(&sm, addk + (size_t)mt * 64 * CD, CD,
                     Wval + (size_t)(2 * h + 1) * CD * CD, CD,
                     nullptr, nullptr, CD, acc);
        // v2 rows go straight to g_B segment [256,512) of head h (unscaled)
        store_tile(acc, g_B + ((size_t)h * SEG + 256 + mt * 64) * CD, CD,
                   bval + (2 * h + 1) * CD);
    } else if (b < 209) {
        int bb = b - 81;                 // 0..127
        float (*tile)[33] = (float(*)[33])(&sm.As[0][0][0]);   // reuse smem (32*33*4 = 4.2KB)
        int h  = bb >> 4;                // 8 heads
        int sub = bb & 15;               // 8 rt x 2 column-halves
        int rt = sub >> 1, chalf = sub & 1;
        int r0 = rt * 32;
        int rr = tid & 31, cl = tid >> 5;
        int cc2 = tid & 31, rl = tid >> 5;
#pragma unroll
        for (int ct = 0; ct < 4; ct++) {
            int c0 = chalf * 128 + ct * 32;
#pragma unroll
            for (int i = 0; i < 4; i++) {
                int cc = cl + i * 8;
                tile[cc][rr] = Wval[((size_t)(2 * h) * CD + (c0 + cc)) * CD + (r0 + rr)];
            }
            __syncthreads();
#pragma unroll
            for (int i = 0; i < 4; i++) {
                int rr2 = rl + i * 8;
                g_B[((size_t)h * SEG + (r0 + rr2)) * CD + (c0 + cc2)] = tile[cc2][rr2];
            }
            __syncthreads();
        }
    } else {
        int c = tid;
#pragma unroll
        for (int h = 0; h < NH; h++)
            g_B[((size_t)h * SEG + 512) * CD + c] = bval[(2 * h) * CD + c];
    }
}

__global__ void __launch_bounds__(256) k_idx(const float* __restrict__ refp,
                                             const int* __restrict__ iss,
                                             const int* __restrict__ lstart) {
    int gid = blockIdx.x * 256 + threadIdx.x;    // 1024*128
    int lq = gid >> 7, r2 = gid & 127;
    int l = (r2 >> 2) & 3;
    float2 off = *(const float2*)(g_off + (size_t)lq * CD + r2 * 2);
    float2 rp  = *(const float2*)(refp + ((size_t)lq * NL + l) * 2);
    int H = iss[l * 2], W = iss[l * 2 + 1];
    float loc0 = rp.x + off.x / (float)W;   // wh = [W, H]
    float loc1 = rp.y + off.y / (float)H;
    loc0 = fminf(fmaxf(loc0, 0.f), 0.999f);
    loc1 = fminf(fmaxf(loc1, 0.f), 0.999f);
    int i0 = (int)(loc0 * (float)H);        // idx = loc * [H, W]
    int i1 = (int)(loc1 * (float)W);
    int flat = i0 + i1 * H + lstart[l];
    g_fidx[(size_t)r2 * LQ + lq] = flat;    // r2 = h*16 + l*4 + p
}

// L3: blocks [0,512): T GEMM + fused deflog ; [512,640): add-key logits
__global__ void __launch_bounds__(256, 2) k_T_addlog(const float* __restrict__ q,
                                                     const float* __restrict__ IF,
                                                     const float* __restrict__ Wattn) {
    __shared__ GSmem sm;
    ull acc[8][4];
    if (blockIdx.x < 512) {
        int hl = blockIdx.x >> 4, rcl = blockIdx.x & 15;
        gemm_core<2>(&sm, q + (size_t)rcl * CD, 16 * CD, nullptr, 0,
                     g_fidx + hl * 4096 + rcl * 256, IF, 256, acc);
        // fused deflog: logit[p, lq] = Wattn[hl][p*64 + i, :] . Ttile[i, :]
        int h = hl >> 2, l = hl & 3;
        const int tid = threadIdx.x;
        const int mrow = (tid >> 5) << 3;
        const int j0   = (tid & 31) << 2;
        const int lane = tid & 31;
#pragma unroll
        for (int i = 0; i < 8; i++) {
            float o[8];
#pragma unroll
            for (int jj = 0; jj < 4; jj++) unpack2(acc[i][jj], o[2*jj], o[2*jj+1]);
            int ri = mrow + i;
            int lq = rcl + 16 * ri;
#pragma unroll
            for (int p = 0; p < 4; p++) {
                const float* wr = Wattn + (((size_t)hl * 256) + (size_t)(p * 64 + ri)) * CD;
                float4 w0 = *(const float4*)(wr + j0);
                float4 w1 = *(const float4*)(wr + j0 + 128);
                float part = o[0]*w0.x + o[1]*w0.y + o[2]*w0.z + o[3]*w0.w
                           + o[4]*w1.x + o[5]*w1.y + o[6]*w1.z + o[7]*w1.w;
#pragma unroll
                for (int off = 16; off > 0; off >>= 1)
                    part += __shfl_xor_sync(0xffffffffu, part, off);
                if (lane == 0)
                    g_logits[(size_t)h * NLOG * LQ + (size_t)(l * 4 + p) * LQ + lq] = part;
            }
        }
    } else {
        int b = blockIdx.x - 512;
        int h = b >> 4, mt = (b >> 2) & 3, nt = b & 3;
        gemm_core<0>(&sm, g_A2 + (size_t)h * CD * CD + mt * 64 * CD, CD,
                     q + (size_t)nt * 256 * CD, CD, nullptr, nullptr, CD, acc);
        store_tile(acc, g_logits + (size_t)h * NLOG * LQ + (size_t)(16 + mt * 64) * LQ + nt * 256,
                   LQ, nullptr);
    }
}

// L4: fused softmax + kw gather. One warp per (h, lq).
__global__ void __launch_bounds__(256) k_attn_kw(const float* __restrict__ IF) {
    int warp = threadIdx.x >> 5, lane = threadIdx.x & 31;
    int col = blockIdx.x * 8 + warp;            // 8192 total
    int h = col >> 10, lq = col & 1023;
    const float* base = g_logits + (size_t)h * NLOG * LQ + lq;
    float v[9];
    float vmax = -1e30f;
#pragma unroll
    for (int k = 0; k < 9; k++) {
        int s = lane + 32 * k;
        v[k] = (s < NLOG) ? base[(size_t)s * LQ] : -1e30f;
        vmax = fmaxf(vmax, v[k]);
    }
#pragma unroll
    for (int o = 16; o > 0; o >>= 1) vmax = fmaxf(vmax, __shfl_xor_sync(0xffffffffu, vmax, o));
    float sum = 0.f;
#pragma unroll
    for (int k = 0; k < 9; k++) {
        int s = lane + 32 * k;
        v[k] = (s < NLOG) ? expf(v[k] - vmax) : 0.f;
        sum += v[k];
    }
#pragma unroll
    for (int o = 16; o > 0; o >>= 1) sum += __shfl_xor_sync(0xffffffffu, sum, o);
    float inv = 1.f / sum;
    float* arow = g_A + (size_t)lq * KTOT + h * SEG;
    float sa = 0.f;
    float wdef = v[0] * inv;                    // lanes 0..15: deform weights
#pragma unroll
    for (int k = 0; k < 9; k++) {
        int s = lane + 32 * k;
        if (s >= NLOG) continue;
        float w = v[k] * inv;
        if (s < 16) sa += w;                    // keep in register
        else        arow[256 + s - 16] = w;
    }
#pragma unroll
    for (int o = 16; o > 0; o >>= 1) sa += __shfl_xor_sync(0xffffffffu, sa, o);
    if (lane == 0) arow[512] = sa;

    // kw gather: kw[lq, :] = sum_{s<16} wdef_s * IF[fidx[h,s,lq], :]
    int myidx = (lane < 16) ? g_fidx[(h * 16 + lane) * LQ + lq] : 0;
    float acc[8];
#pragma unroll
    for (int j = 0; j < 8; j++) acc[j] = 0.f;
#pragma unroll
    for (int s = 0; s < 16; s++) {
        float w  = __shfl_sync(0xffffffffu, wdef, s);
        int   ix = __shfl_sync(0xffffffffu, myidx, s);
        const float4* row = (const float4*)(IF + (size_t)ix * CD + lane * 8);
        float4 a = row[0], b = row[1];
        acc[0] = fmaf(w, a.x, acc[0]); acc[1] = fmaf(w, a.y, acc[1]);
        acc[2] = fmaf(w, a.z, acc[2]); acc[3] = fmaf(w, a.w, acc[3]);
        acc[4] = fmaf(w, b.x, acc[4]); acc[5] = fmaf(w, b.y, acc[5]);
        acc[6] = fmaf(w, b.z, acc[6]); acc[7] = fmaf(w, b.w, acc[7]);
    }
    float4* out = (float4*)(arow + lane * 8);
    out[0] = make_float4(acc[0], acc[1], acc[2], acc[3]);
    out[1] = make_float4(acc[4], acc[5], acc[6], acc[7]);
}

// fused output GEMM per (head, K-half) -> UNscaled per-(head,half) partials
__global__ void __launch_bounds__(256, 2) k_fused() {
    __shared__ GSmem sm;
    ull acc[8][4];
    int h = blockIdx.x >> 5;
    int sub = blockIdx.x & 31;
    int mt = sub & 15, half = sub >> 4;
    int koff = half ? KH0 : 0;
    int K    = half ? KH1 : KH0;
    gemm_core<1>(&sm, g_A + (size_t)mt * 64 * KTOT + h * SEG + koff, KTOT,
                 g_B + ((size_t)h * SEG + koff) * CD, CD, nullptr, nullptr, K, acc);
    store_tile(acc, g_Cpart + (((size_t)(h * 2 + half) * LQ) + mt * 64) * CD, CD, nullptr);
}

// final: out = q*hw[8] + sum_h hw[h] * (Cpart[2h] + Cpart[2h+1])
__global__ void __launch_bounds__(256) k_out(const float* __restrict__ q,
                                             float* __restrict__ out) {
    int e = blockIdx.x * 256 + threadIdx.x;     // 65536 float4
    int c4 = e & 63;
    float4 qv = ((const float4*)q)[e];
    float4 hw8 = ((const float4*)(g_hw + 8 * CD))[c4];
    float4 r;
    r.x = qv.x * hw8.x; r.y = qv.y * hw8.y; r.z = qv.z * hw8.z; r.w = qv.w * hw8.w;
#pragma unroll
    for (int h = 0; h < NH; h++) {
        float4 hwh = ((const float4*)(g_hw + h * CD))[c4];
        float4 p0 = ((const float4*)(g_Cpart + (size_t)(2 * h) * LQ * CD))[e];
        float4 p1 = ((const float4*)(g_Cpart + (size_t)(2 * h + 1) * LQ * CD))[e];
        r.x = fmaf(hwh.x, p0.x + p1.x, r.x);
        r.y = fmaf(hwh.y, p0.y + p1.y, r.y);
        r.z = fmaf(hwh.z, p0.z + p1.z, r.z);
        r.w = fmaf(hwh.w, p0.w + p1.w, r.w);
    }
    ((float4*)out)[e] = r;
}

extern "C" void kernel_launch(void* const* d_in, const int* in_sizes, int n_in,
                              void* d_out, int out_size) {
    const float* query  = (const float*)d_in[0];
    const float* refp   = (const float*)d_in[1];
    const float* IF     = (const float*)d_in[2];
    const int*   iss    = (const int*)d_in[3];
    const float* addk   = (const float*)d_in[4];
    const int*   lstart = (const int*)d_in[5];
    const float* Woff   = (const float*)d_in[6];
    const float* boff   = (const float*)d_in[7];
    const float* Wattn  = (const float*)d_in[8];
    const float* Wval   = (const float*)d_in[9];
    const float* bval   = (const float*)d_in[10];
    const float* Wmix   = (const float*)d_in[11];
    float* out = (float*)d_out;

    k_pre<<<210, 256>>>(query, Woff, boff, Wmix, addk, Wattn, Wval, bval);
    k_idx<<<512, 256>>>(refp, iss, lstart);
    k_T_addlog<<<640, 256>>>(query, IF, Wattn);
    k_attn_kw<<<1024, 256>>>(IF);
    k_fused<<<256, 256>>>();
    k_out<<<256, 256>>>(query, out);
}

// round 16
// speedup vs baseline: 1.0507x; 1.0331x over previous
#include <cuda_runtime.h>
#include <math.h>

#define LQ    1024
#define CD    256
#define NH    8
#define NL    4
#define NLOG  272          // 16 deform + 256 add-key logits
#define SEG   528          // 256 kw + 256 attn_add + 1 sa + 15 pad (stays zero)
#define KTOT  (NH*SEG)     // 4224
#define KH0   272
#define KH1   256

typedef unsigned long long ull;

__device__ __forceinline__ ull f2fma(ull a, ull b, ull c) {
    ull d; asm("fma.rn.f32x2 %0, %1, %2, %3;" : "=l"(d) : "l"(a), "l"(b), "l"(c)); return d;
}
__device__ __forceinline__ ull splat2(float x) {
    ull d; asm("mov.b64 %0, {%1, %1};" : "=l"(d) : "f"(x)); return d;
}
__device__ __forceinline__ void unpack2(ull v, float& lo, float& hi) {
    asm("mov.b64 {%0, %1}, %2;" : "=f"(lo), "=f"(hi) : "l"(v));
}
__device__ __forceinline__ void cpasync16(unsigned s, const void* g) {
    asm volatile("cp.async.cg.shared.global [%0], [%1], 16;" :: "r"(s), "l"(g));
}
#define CP_COMMIT() asm volatile("cp.async.commit_group;" ::: "memory")
#define CP_WAIT0()  asm volatile("cp.async.wait_group 0;" ::: "memory")

// ---------------- scratch ----------------
__device__ __align__(16) float g_hw[9*CD];
__device__ __align__(16) float g_off[LQ*CD];
__device__ __align__(16) int   g_fidx[NH*16*LQ];
__device__ __align__(16) float g_logits[NH*NLOG*LQ];    // K-half-0 partial logits
__device__ __align__(16) float g_logits2[NH*NLOG*LQ];   // K-half-1 partial logits
__device__ __align__(16) float g_A2[NH*CD*CD];
__device__ __align__(16) float g_A[LQ*KTOT];
__device__ __align__(16) float g_B[KTOT*CD];
__device__ __align__(16) float g_Cpart[NH*2*LQ*CD];

struct GSmem {
    float As[2][16][64];     // 8.2 KB
    float Bs[2][16][264];    // 33.8 KB  -> total 42 KB, 2 CTA/SM fits
};

// Thread column mapping (all GEMMs + epilogues):
//   j0 = (tid & 31) * 4 ; thread owns cols [j0, j0+4) and [j0+128, j0+132)
//   -> LDS.128 lane stride 16B: conflict-free smem reads.

// ---------------- 64x256 GEMM core (K mult of 16) ----------------
// MODE 0: acc += A[64xK] * B^T (B row-major [256][K]; reg prefetch)
// MODE 1: acc += A[64xK] * B   (B row-major [K][256]; cp.async)
// MODE 2: MODE 1 with gathered rows IF[gidx[k]]
template<int MODE>
__device__ __forceinline__ void gemm_core(
    GSmem* sm,
    const float* __restrict__ A, int a_row_stride,
    const float* __restrict__ B, int ldb,
    const int* __restrict__ gidx, const float* __restrict__ IF,
    int K, ull acc[8][4])
{
    const int tid  = threadIdx.x;
    const int mrow = (tid >> 5) << 3;
    const int j0   = (tid & 31) << 2;
#pragma unroll
    for (int i = 0; i < 8; i++)
#pragma unroll
        for (int j = 0; j < 4; j++) acc[i][j] = 0ull;

    const int ar = tid >> 2, ac = (tid & 3) << 2;
    const int brow = tid >> 4, bcol = (tid & 15) << 2;
    unsigned bs_sm[2];
    bs_sm[0] = (unsigned)__cvta_generic_to_shared(&sm->Bs[0][brow][bcol]);
    bs_sm[1] = (unsigned)__cvta_generic_to_shared(&sm->Bs[1][brow][bcol]);

    float4 pa, pb0, pb1, pb2, pb3;

    // ---- prologue: tile 0 ----
    pa = *(const float4*)(A + (size_t)ar * a_row_stride + ac);
    if (MODE == 0) {
        const float* br = B + (size_t)tid * ldb;
        pb0 = ((const float4*)br)[0]; pb1 = ((const float4*)br)[1];
        pb2 = ((const float4*)br)[2]; pb3 = ((const float4*)br)[3];
        sm->Bs[0][0][tid]  = pb0.x; sm->Bs[0][1][tid]  = pb0.y; sm->Bs[0][2][tid]  = pb0.z; sm->Bs[0][3][tid]  = pb0.w;
        sm->Bs[0][4][tid]  = pb1.x; sm->Bs[0][5][tid]  = pb1.y; sm->Bs[0][6][tid]  = pb1.z; sm->Bs[0][7][tid]  = pb1.w;
        sm->Bs[0][8][tid]  = pb2.x; sm->Bs[0][9][tid]  = pb2.y; sm->Bs[0][10][tid] = pb2.z; sm->Bs[0][11][tid] = pb2.w;
        sm->Bs[0][12][tid] = pb3.x; sm->Bs[0][13][tid] = pb3.y; sm->Bs[0][14][tid] = pb3.z; sm->Bs[0][15][tid] = pb3.w;
    } else {
        const float* br = (MODE == 2) ? (IF + (size_t)gidx[brow] * CD)
                                      : (B + (size_t)brow * ldb);
#pragma unroll
        for (int i = 0; i < 4; i++)
            cpasync16(bs_sm[0] + i * 256, br + bcol + i * 64);
        CP_COMMIT();
        CP_WAIT0();
    }
    sm->As[0][ac + 0][ar] = pa.x; sm->As[0][ac + 1][ar] = pa.y;
    sm->As[0][ac + 2][ar] = pa.z; sm->As[0][ac + 3][ar] = pa.w;
    __syncthreads();

    int buf = 0;
    for (int k0 = 16;; k0 += 16) {
        const bool more = (k0 < K);
        const int nb = buf ^ 1;
        if (more) {
            pa = *(const float4*)(A + (size_t)ar * a_row_stride + k0 + ac);
            if (MODE == 0) {
                const float* br = B + (size_t)tid * ldb + k0;
                pb0 = ((const float4*)br)[0]; pb1 = ((const float4*)br)[1];
                pb2 = ((const float4*)br)[2]; pb3 = ((const float4*)br)[3];
            } else {
                const float* br = (MODE == 2) ? (IF + (size_t)gidx[k0 + brow] * CD)
                                              : (B + (size_t)(k0 + brow) * ldb);
#pragma unroll
                for (int i = 0; i < 4; i++)
                    cpasync16(bs_sm[nb] + i * 256, br + bcol + i * 64);
                CP_COMMIT();
            }
        }
#pragma unroll
        for (int k = 0; k < 16; k++) {
            float4 av0 = *(const float4*)&sm->As[buf][k][mrow];
            float4 av1 = *(const float4*)&sm->As[buf][k][mrow + 4];
            ulonglong2 bl0 = *(const ulonglong2*)&sm->Bs[buf][k][j0];
            ulonglong2 bl1 = *(const ulonglong2*)&sm->Bs[buf][k][j0 + 128];
            ull b0 = bl0.x, b1 = bl0.y, b2 = bl1.x, b3 = bl1.y;
            float a8[8] = {av0.x, av0.y, av0.z, av0.w, av1.x, av1.y, av1.z, av1.w};
#pragma unroll
            for (int i = 0; i < 8; i++) {
                ull ai = splat2(a8[i]);
                acc[i][0] = f2fma(ai, b0, acc[i][0]);
                acc[i][1] = f2fma(ai, b1, acc[i][1]);
                acc[i][2] = f2fma(ai, b2, acc[i][2]);
                acc[i][3] = f2fma(ai, b3, acc[i][3]);
            }
        }
        if (!more) break;
        sm->As[nb][ac + 0][ar] = pa.x; sm->As[nb][ac + 1][ar] = pa.y;
        sm->As[nb][ac + 2][ar] = pa.z; sm->As[nb][ac + 3][ar] = pa.w;
        if (MODE == 0) {
            sm->Bs[nb][0][tid]  = pb0.x; sm->Bs[nb][1][tid]  = pb0.y; sm->Bs[nb][2][tid]  = pb0.z; sm->Bs[nb][3][tid]  = pb0.w;
            sm->Bs[nb][4][tid]  = pb1.x; sm->Bs[nb][5][tid]  = pb1.y; sm->Bs[nb][6][tid]  = pb1.z; sm->Bs[nb][7][tid]  = pb1.w;
            sm->Bs[nb][8][tid]  = pb2.x; sm->Bs[nb][9][tid]  = pb2.y; sm->Bs[nb][10][tid] = pb2.z; sm->Bs[nb][11][tid] = pb2.w;
            sm->Bs[nb][12][tid] = pb3.x; sm->Bs[nb][13][tid] = pb3.y; sm->Bs[nb][14][tid] = pb3.z; sm->Bs[nb][15][tid] = pb3.w;
        } else {
            CP_WAIT0();
        }
        __syncthreads();
        buf = nb;
    }
}

// columns: [j0, j0+4) from acc[.][0..1], [j0+128, j0+132) from acc[.][2..3]
__device__ __forceinline__ void store_tile(ull acc[8][4], float* __restrict__ C,
                                           int ldc, const float* __restrict__ bias) {
    const int tid  = threadIdx.x;
    const int mrow = (tid >> 5) << 3;
    const int j0   = (tid & 31) << 2;
#pragma unroll
    for (int i = 0; i < 8; i++) {
        float o[8];
#pragma unroll
        for (int jj = 0; jj < 4; jj++) unpack2(acc[i][jj], o[2*jj], o[2*jj+1]);
        if (bias) {
#pragma unroll
            for (int j = 0; j < 4; j++) o[j] += bias[j0 + j];
#pragma unroll
            for (int j = 4; j < 8; j++) o[j] += bias[j0 + 124 + j];   // 128 + j0 + (j-4)
        }
        float* cr = C + (size_t)(mrow + i) * ldc;
        *(float4*)(cr + j0)       = *(const float4*)(o + 0);
        *(float4*)(cr + j0 + 128) = *(const float4*)(o + 4);
    }
}

// ---------------- kernels ----------------

// L1 (210 blocks):
//   [0,16)    off = q @ Woff^T + boff
//   16        head-mix softmax
//   [17,49)   A2 GEMMs
//   [49,81)   v2 GEMMs -> stored DIRECTLY into g_B rows [256,512) (no hw)
//   [81,209)  Wval^T transpose, 32x128 per block -> g_B rows [0,256) (no hw)
//   209       bias rows -> g_B row 512 per head (no hw)
__global__ void __launch_bounds__(256, 2) k_pre(const float* __restrict__ q,
                                                const float* __restrict__ Woff,
                                                const float* __restrict__ boff,
                                                const float* __restrict__ Wmix,
                                                const float* __restrict__ addk,
                                                const float* __restrict__ Wattn,
                                                const float* __restrict__ Wval,
                                                const float* __restrict__ bval) {
    __shared__ GSmem sm;
    ull acc[8][4];
    int b = blockIdx.x;
    int tid = threadIdx.x;
    if (b < 16) {
        gemm_core<0>(&sm, q + (size_t)b * 64 * CD, CD, Woff, CD, nullptr, nullptr, CD, acc);
        store_tile(acc, g_off + (size_t)b * 64 * CD, CD, boff);
    } else if (b == 16) {
        int c = tid;
        float v[9], m = -1e30f;
#pragma unroll
        for (int j = 0; j < 9; j++) { v[j] = Wmix[c * 9 + j]; m = fmaxf(m, v[j]); }
        float s = 0.f;
#pragma unroll
        for (int j = 0; j < 9; j++) { v[j] = expf(v[j] - m); s += v[j]; }
        float inv = 1.f / s;
#pragma unroll
        for (int j = 0; j < 9; j++) g_hw[j * CD + c] = v[j] * inv;
    } else if (b < 49) {
        int bb = b - 17;
        int mat = bb >> 2, mt = bb & 3;
        gemm_core<0>(&sm, addk + (size_t)mt * 64 * CD, CD,
                     Wattn + (size_t)(mat * 4 + 4) * CD * CD, CD,
                     nullptr, nullptr, CD, acc);
        store_tile(acc, g_A2 + (size_t)mat * CD * CD + mt * 64 * CD, CD, nullptr);
    } else if (b < 81) {
        int bb = b - 49;
        int h = bb >> 2, mt = bb & 3;
        gemm_core<0>(&sm, addk + (size_t)mt * 64 * CD, CD,
                     Wval + (size_t)(2 * h + 1) * CD * CD, CD,
                     nullptr, nullptr, CD, acc);
        // v2 rows go straight to g_B segment [256,512) of head h (unscaled)
        store_tile(acc, g_B + ((size_t)h * SEG + 256 + mt * 64) * CD, CD,
                   bval + (2 * h + 1) * CD);
    } else if (b < 209) {
        int bb = b - 81;                 // 0..127
        float (*tile)[33] = (float(*)[33])(&sm.As[0][0][0]);   // reuse smem
        int h  = bb >> 4;                // 8 heads
        int sub = bb & 15;               // 8 rt x 2 column-halves
        int rt = sub >> 1, chalf = sub & 1;
        int r0 = rt * 32;
        int rr = tid & 31, cl = tid >> 5;
        int cc2 = tid & 31, rl = tid >> 5;
#pragma unroll
        for (int ct = 0; ct < 4; ct++) {
            int c0 = chalf * 128 + ct * 32;
#pragma unroll
            for (int i = 0; i < 4; i++) {
                int cc = cl + i * 8;
                tile[cc][rr] = Wval[((size_t)(2 * h) * CD + (c0 + cc)) * CD + (r0 + rr)];
            }
            __syncthreads();
#pragma unroll
            for (int i = 0; i < 4; i++) {
                int rr2 = rl + i * 8;
                g_B[((size_t)h * SEG + (r0 + rr2)) * CD + (c0 + cc2)] = tile[cc2][rr2];
            }
            __syncthreads();
        }
    } else {
        int c = tid;
#pragma unroll
        for (int h = 0; h < NH; h++)
            g_B[((size_t)h * SEG + 512) * CD + c] = bval[(2 * h) * CD + c];
    }
}

__global__ void __launch_bounds__(256) k_idx(const float* __restrict__ refp,
                                             const int* __restrict__ iss,
                                             const int* __restrict__ lstart) {
    int gid = blockIdx.x * 256 + threadIdx.x;    // 1024*128
    int lq = gid >> 7, r2 = gid & 127;
    int l = (r2 >> 2) & 3;
    float2 off = *(const float2*)(g_off + (size_t)lq * CD + r2 * 2);
    float2 rp  = *(const float2*)(refp + ((size_t)lq * NL + l) * 2);
    int H = iss[l * 2], W = iss[l * 2 + 1];
    float loc0 = rp.x + off.x / (float)W;   // wh = [W, H]
    float loc1 = rp.y + off.y / (float)H;
    loc0 = fminf(fmaxf(loc0, 0.f), 0.999f);
    loc1 = fminf(fmaxf(loc1, 0.f), 0.999f);
    int i0 = (int)(loc0 * (float)H);        // idx = loc * [H, W]
    int i1 = (int)(loc1 * (float)W);
    int flat = i0 + i1 * H + lstart[l];
    g_fidx[(size_t)r2 * LQ + lq] = flat;    // r2 = h*16 + l*4 + p
}

// L3 (1280 blocks): K-split GEMMs, each half writes partial logits to its buffer.
//   [0,1024):   T GEMM halves + fused deflog: b = hl*32 + half*16 + rcl
//   [1024,1280): add-key logit halves: (half, h, mt, nt)
__global__ void __launch_bounds__(256, 2) k_T_addlog(const float* __restrict__ q,
                                                     const float* __restrict__ IF,
                                                     const float* __restrict__ Wattn) {
    __shared__ GSmem sm;
    ull acc[8][4];
    if (blockIdx.x < 1024) {
        int hl = blockIdx.x >> 5;
        int sub = blockIdx.x & 31;
        int half = sub >> 4, rcl = sub & 15;
        int koff = half * 128;
        float* dst = half ? g_logits2 : g_logits;
        gemm_core<2>(&sm, q + (size_t)rcl * CD + koff, 16 * CD, nullptr, 0,
                     g_fidx + hl * 4096 + rcl * 256 + koff, IF, 128, acc);
        // fused deflog (partial over this K-half)
        int h = hl >> 2, l = hl & 3;
        const int tid = threadIdx.x;
        const int mrow = (tid >> 5) << 3;
        const int j0   = (tid & 31) << 2;
        const int lane = tid & 31;
#pragma unroll
        for (int i = 0; i < 8; i++) {
            float o[8];
#pragma unroll
            for (int jj = 0; jj < 4; jj++) unpack2(acc[i][jj], o[2*jj], o[2*jj+1]);
            int ri = mrow + i;
            int lq = rcl + 16 * ri;
#pragma unroll
            for (int p = 0; p < 4; p++) {
                const float* wr = Wattn + (((size_t)hl * 256) + (size_t)(p * 64 + ri)) * CD;
                float4 w0 = *(const float4*)(wr + j0);
                float4 w1 = *(const float4*)(wr + j0 + 128);
                float part = o[0]*w0.x + o[1]*w0.y + o[2]*w0.z + o[3]*w0.w
                           + o[4]*w1.x + o[5]*w1.y + o[6]*w1.z + o[7]*w1.w;
#pragma unroll
                for (int off = 16; off > 0; off >>= 1)
                    part += __shfl_xor_sync(0xffffffffu, part, off);
                if (lane == 0)
                    dst[(size_t)h * NLOG * LQ + (size_t)(l * 4 + p) * LQ + lq] = part;
            }
        }
    } else {
        int b = blockIdx.x - 1024;
        int half = b >> 7;
        int b3 = b & 127;
        int h = b3 >> 4, mt = (b3 >> 2) & 3, nt = b3 & 3;
        int koff = half * 128;
        float* dst = half ? g_logits2 : g_logits;
        gemm_core<0>(&sm, g_A2 + ((size_t)h * CD + mt * 64) * CD + koff, CD,
                     q + (size_t)nt * 256 * CD + koff, CD, nullptr, nullptr, 128, acc);
        store_tile(acc, dst + (size_t)h * NLOG * LQ + (size_t)(16 + mt * 64) * LQ + nt * 256,
                   LQ, nullptr);
    }
}

// L4: fused softmax + kw gather, smem-staged coalesced logit reads.
// One block per (h, 8 consecutive lq); one warp per lq.
__global__ void __launch_bounds__(256) k_attn_kw(const float* __restrict__ IF) {
    __shared__ float lg[NLOG][9];   // summed partial logits, padded row
    __shared__ int   fx[16][8];
    int tid = threadIdx.x;
    int warp = tid >> 5, lane = tid & 31;
    int h = blockIdx.x >> 7;                 // 128 blocks per head
    int lq0 = (blockIdx.x & 127) << 3;
    const float* baseA = g_logits  + (size_t)h * NLOG * LQ + lq0;
    const float* baseB = g_logits2 + (size_t)h * NLOG * LQ + lq0;
    for (int i = tid; i < NLOG * 8; i += 256) {
        int s = i >> 3, j = i & 7;
        lg[s][j] = baseA[(size_t)s * LQ + j] + baseB[(size_t)s * LQ + j];
    }
    if (tid < 128) {
        int s = tid >> 3, j = tid & 7;
        fx[s][j] = g_fidx[(h * 16 + s) * LQ + lq0 + j];
    }
    __syncthreads();

    int lq = lq0 + warp;
    float v[9];
    float vmax = -1e30f;
#pragma unroll
    for (int k = 0; k < 9; k++) {
        int s = lane + 32 * k;
        v[k] = (s < NLOG) ? lg[s][warp] : -1e30f;
        vmax = fmaxf(vmax, v[k]);
    }
#pragma unroll
    for (int o = 16; o > 0; o >>= 1) vmax = fmaxf(vmax, __shfl_xor_sync(0xffffffffu, vmax, o));
    float sum = 0.f;
#pragma unroll
    for (int k = 0; k < 9; k++) {
        int s = lane + 32 * k;
        v[k] = (s < NLOG) ? expf(v[k] - vmax) : 0.f;
        sum += v[k];
    }
#pragma unroll
    for (int o = 16; o > 0; o >>= 1) sum += __shfl_xor_sync(0xffffffffu, sum, o);
    float inv = 1.f / sum;
    float* arow = g_A + (size_t)lq * KTOT + h * SEG;
    float sa = 0.f;
    float wdef = v[0] * inv;                    // lanes 0..15: deform weights
#pragma unroll
    for (int k = 0; k < 9; k++) {
        int s = lane + 32 * k;
        if (s >= NLOG) continue;
        float w = v[k] * inv;
        if (s < 16) sa += w;                    // keep in register
        else        arow[256 + s - 16] = w;
    }
#pragma unroll
    for (int o = 16; o > 0; o >>= 1) sa += __shfl_xor_sync(0xffffffffu, sa, o);
    if (lane == 0) arow[512] = sa;

    // kw gather: kw[lq, :] = sum_{s<16} wdef_s * IF[fidx[h,s,lq], :]
    int myidx = (lane < 16) ? fx[lane][warp] : 0;
    float acc[8];
#pragma unroll
    for (int j = 0; j < 8; j++) acc[j] = 0.f;
#pragma unroll
    for (int s = 0; s < 16; s++) {
        float w  = __shfl_sync(0xffffffffu, wdef, s);
        int   ix = __shfl_sync(0xffffffffu, myidx, s);
        const float4* row = (const float4*)(IF + (size_t)ix * CD + lane * 8);
        float4 a = row[0], b = row[1];
        acc[0] = fmaf(w, a.x, acc[0]); acc[1] = fmaf(w, a.y, acc[1]);
        acc[2] = fmaf(w, a.z, acc[2]); acc[3] = fmaf(w, a.w, acc[3]);
        acc[4] = fmaf(w, b.x, acc[4]); acc[5] = fmaf(w, b.y, acc[5]);
        acc[6] = fmaf(w, b.z, acc[6]); acc[7] = fmaf(w, b.w, acc[7]);
    }
    float4* out = (float4*)(arow + lane * 8);
    out[0] = make_float4(acc[0], acc[1], acc[2], acc[3]);
    out[1] = make_float4(acc[4], acc[5], acc[6], acc[7]);
}

// fused output GEMM per (head, K-half) -> UNscaled per-(head,half) partials
__global__ void __launch_bounds__(256, 2) k_fused() {
    __shared__ GSmem sm;
    ull acc[8][4];
    int h = blockIdx.x >> 5;
    int sub = blockIdx.x & 31;
    int mt = sub & 15, half = sub >> 4;
    int koff = half ? KH0 : 0;
    int K    = half ? KH1 : KH0;
    gemm_core<1>(&sm, g_A + (size_t)mt * 64 * KTOT + h * SEG + koff, KTOT,
                 g_B + ((size_t)h * SEG + koff) * CD, CD, nullptr, nullptr, K, acc);
    store_tile(acc, g_Cpart + (((size_t)(h * 2 + half) * LQ) + mt * 64) * CD, CD, nullptr);
}

// final: out = q*hw[8] + sum_h hw[h] * (Cpart[2h] + Cpart[2h+1])
__global__ void __launch_bounds__(256) k_out(const float* __restrict__ q,
                                             float* __restrict__ out) {
    int e = blockIdx.x * 256 + threadIdx.x;     // 65536 float4
    int c4 = e & 63;
    float4 qv = ((const float4*)q)[e];
    float4 hw8 = ((const float4*)(g_hw + 8 * CD))[c4];
    float4 r;
    r.x = qv.x * hw8.x; r.y = qv.y * hw8.y; r.z = qv.z * hw8.z; r.w = qv.w * hw8.w;
#pragma unroll
    for (int h = 0; h < NH; h++) {
        float4 hwh = ((const float4*)(g_hw + h * CD))[c4];
        float4 p0 = ((const float4*)(g_Cpart + (size_t)(2 * h) * LQ * CD))[e];
        float4 p1 = ((const float4*)(g_Cpart + (size_t)(2 * h + 1) * LQ * CD))[e];
        r.x = fmaf(hwh.x, p0.x + p1.x, r.x);
        r.y = fmaf(hwh.y, p0.y + p1.y, r.y);
        r.z = fmaf(hwh.z, p0.z + p1.z, r.z);
        r.w = fmaf(hwh.w, p0.w + p1.w, r.w);
    }
    ((float4*)out)[e] = r;
}

extern "C" void kernel_launch(void* const* d_in, const int* in_sizes, int n_in,
                              void* d_out, int out_size) {
    const float* query  = (const float*)d_in[0];
    const float* refp   = (const float*)d_in[1];
    const float* IF     = (const float*)d_in[2];
    const int*   iss    = (const int*)d_in[3];
    const float* addk   = (const float*)d_in[4];
    const int*   lstart = (const int*)d_in[5];
    const float* Woff   = (const float*)d_in[6];
    const float* boff   = (const float*)d_in[7];
    const float* Wattn  = (const float*)d_in[8];
    const float* Wval   = (const float*)d_in[9];
    const float* bval   = (const float*)d_in[10];
    const float* Wmix   = (const float*)d_in[11];
    float* out = (float*)d_out;

    k_pre<<<210, 256>>>(query, Woff, boff, Wmix, addk, Wattn, Wval, bval);
    k_idx<<<512, 256>>>(refp, iss, lstart);
    k_T_addlog<<<1280, 256>>>(query, IF, Wattn);
    k_attn_kw<<<1024, 256>>>(IF);
    k_fused<<<256, 256>>>();
    k_out<<<256, 256>>>(query, out);
}